// round 12
// baseline (speedup 1.0000x reference)
#include <cuda_runtime.h>
#include <cstdint>

#define NBATCH 4
#define SEQ    4096
#define HID    2048
#define NE     64
#define NTOK   (NBATCH * SEQ)   // 16384
#define TTILE  128
#define KC     32
#define NCHUNK (HID / KC)       // 64

// dynamic smem layout (float offsets): fragment-order planes, pitch 33
#define OFF_AH 0
#define OFF_AL 4224              // 4 kstep * 8 mtile * 4 reg * 33
#define OFF_BH 8448
#define OFF_BL 10560             // 4 kstep * 8 ntile * 2 reg * 33
#define DSM_FLOATS 12672
#define DSM_BYTES  (DSM_FLOATS * 4)   // 50688

__device__ float g_ssum[NBATCH * NE];
__device__ int   g_cnt [NBATCH * NE];

__device__ __forceinline__ uint32_t tf32cvt(float v) {
    uint32_t r; asm("cvt.rna.tf32.f32 %0, %1;" : "=r"(r) : "f"(v)); return r;
}
__device__ __forceinline__ void mma8(float* d, const uint32_t* a, const uint32_t* b) {
    asm volatile(
        "mma.sync.aligned.m16n8k8.row.col.f32.tf32.tf32.f32 "
        "{%0,%1,%2,%3}, {%4,%5,%6,%7}, {%8,%9}, {%0,%1,%2,%3};"
        : "+f"(d[0]), "+f"(d[1]), "+f"(d[2]), "+f"(d[3])
        : "r"(a[0]), "r"(a[1]), "r"(a[2]), "r"(a[3]), "r"(b[0]), "r"(b[1]));
}

__global__ void zero_kernel() {
    int t = threadIdx.x;
    if (t < NBATCH * NE) { g_ssum[t] = 0.0f; g_cnt[t] = 0; }
}

extern __shared__ float dsm[];

__global__ __launch_bounds__(128, 1)
void gate_kernel(const float* __restrict__ x, const float* __restrict__ w,
                 float* __restrict__ out)
{
    const int tid  = threadIdx.x;
    const int lane = tid & 31, warp = tid >> 5;
    const int tok0 = blockIdx.x * TTILE;

    __shared__ int   cnt_s[NE];
    __shared__ float psum[128];
    __shared__ float rzs[128];
    if (tid < NE) cnt_s[tid] = 0;

    float* Ah = dsm + OFF_AH;
    float* Al = dsm + OFF_AL;
    float* Bh = dsm + OFF_BH;
    float* Bl = dsm + OFF_BL;

    // staging coordinates
    const float* xrow = x + (size_t)(tok0 + tid) * HID;       // token = tid
    const int amt = tid >> 4, rr = tid & 15, g = rr & 7, rb = rr >> 3;
    const int be = tid >> 1, bk = tid & 1;                    // expert row, k-half
    const float* wrow = w + (size_t)be * HID + bk * 16;
    const int bnt = be >> 3, bne = be & 7;

    float acc[2][8][4];
    #pragma unroll
    for (int mt = 0; mt < 2; mt++)
        #pragma unroll
        for (int nt = 0; nt < 8; nt++)
            #pragma unroll
            for (int r = 0; r < 4; r++) acc[mt][nt][r] = 0.0f;

    float4 xr[8], wr[4];
    #pragma unroll
    for (int i = 0; i < 8; i++) xr[i] = *(const float4*)(xrow + i * 4);
    #pragma unroll
    for (int q = 0; q < 4; q++) wr[q] = *(const float4*)(wrow + q * 4);

    for (int t = 0; t < NCHUNK; t++) {
        // ---- stage chunk t: cvt hi/lo -> fragment-order smem ----
        #pragma unroll
        for (int i = 0; i < 8; i++) {
            const int kstep = i >> 1;
            const int r = rb + ((i & 1) << 1);
            const int base = ((kstep * 8 + amt) * 4 + r) * 33 + g * 4;
            const float v[4] = {xr[i].x, xr[i].y, xr[i].z, xr[i].w};
            #pragma unroll
            for (int j = 0; j < 4; j++) {
                const float hf = __uint_as_float(tf32cvt(v[j]));
                Ah[base + j] = hf;
                Al[base + j] = __uint_as_float(tf32cvt(v[j] - hf));
            }
        }
        #pragma unroll
        for (int q = 0; q < 4; q++) {
            const int kk0 = bk * 16 + q * 4;
            const int kstep = kk0 >> 3, reg = (kk0 & 7) >> 2;
            const int base = ((kstep * 8 + bnt) * 2 + reg) * 33 + bne * 4;
            const float v[4] = {wr[q].x, wr[q].y, wr[q].z, wr[q].w};
            #pragma unroll
            for (int j = 0; j < 4; j++) {
                const float hf = __uint_as_float(tf32cvt(v[j]));
                Bh[base + j] = hf;
                Bl[base + j] = __uint_as_float(tf32cvt(v[j] - hf));
            }
        }
        __syncthreads();

        // prefetch raw chunk t+1 (overlaps HMMA below)
        if (t + 1 < NCHUNK) {
            const int kb = (t + 1) * KC;
            #pragma unroll
            for (int i = 0; i < 8; i++) xr[i] = *(const float4*)(xrow + kb + i * 4);
            #pragma unroll
            for (int q = 0; q < 4; q++) wr[q] = *(const float4*)(wrow + kb + q * 4);
        }

        // ---- compute chunk t ----
        #pragma unroll
        for (int ks = 0; ks < 4; ks++) {
            uint32_t bhf[8][2], blf[8][2];
            #pragma unroll
            for (int nt = 0; nt < 8; nt++) {
                const int p = ((ks * 8 + nt) * 2) * 33 + lane;
                bhf[nt][0] = __float_as_uint(Bh[p]);
                bhf[nt][1] = __float_as_uint(Bh[p + 33]);
                blf[nt][0] = __float_as_uint(Bl[p]);
                blf[nt][1] = __float_as_uint(Bl[p + 33]);
            }
            #pragma unroll
            for (int mt = 0; mt < 2; mt++) {
                const int q = ((ks * 8 + warp * 2 + mt) * 4) * 33 + lane;
                uint32_t ahf[4], alf[4];
                #pragma unroll
                for (int r = 0; r < 4; r++) {
                    ahf[r] = __float_as_uint(Ah[q + r * 33]);
                    alf[r] = __float_as_uint(Al[q + r * 33]);
                }
                #pragma unroll
                for (int nt = 0; nt < 8; nt++) {
                    mma8(acc[mt][nt], ahf, bhf[nt]);   // hi*hi
                    mma8(acc[mt][nt], ahf, blf[nt]);   // hi*lo
                    mma8(acc[mt][nt], alf, bhf[nt]);   // lo*hi
                }
            }
        }
        __syncthreads();
    }

    // ---- dump logits to smem (overlay on A region), pitch 65 ----
    float* L = dsm;
    const int gg = lane >> 2, cc = lane & 3;
    #pragma unroll
    for (int mt = 0; mt < 2; mt++) {
        const int trow = (warp * 2 + mt) * 16 + gg;
        #pragma unroll
        for (int nt = 0; nt < 8; nt++) {
            const int e0 = nt * 8 + cc * 2;
            L[trow * 65 + e0]           = acc[mt][nt][0];
            L[trow * 65 + e0 + 1]       = acc[mt][nt][1];
            L[(trow + 8) * 65 + e0]     = acc[mt][nt][2];
            L[(trow + 8) * 65 + e0 + 1] = acc[mt][nt][3];
        }
    }
    __syncthreads();

    // ---- per-token epilogue: thread tid owns token gt = tok0+tid ----
    const int gt = tok0 + tid;

    // top-4 candidates from mma logits (insertion keeps lower index on ties)
    float tv[4] = {-1e30f, -1e30f, -1e30f, -1e30f};
    int   tix[4] = {0, 0, 0, 0};
    for (int e = 0; e < NE; e++) {
        const float Le = L[tid * 65 + e];
        if (Le > tv[3]) {
            int p = 3;
            while (p > 0 && Le > tv[p - 1]) {
                tv[p] = tv[p - 1]; tix[p] = tix[p - 1]; p--;
            }
            tv[p] = Le; tix[p] = e;
        }
    }

    // exact fp32 recompute of the 4 candidate logits
    float ev[4];
    {
        const float* xg = x + (size_t)gt * HID;
        #pragma unroll
        for (int c = 0; c < 4; c++) {
            const float* wg = w + (size_t)tix[c] * HID;
            float s0 = 0.f, s1 = 0.f, s2 = 0.f, s3 = 0.f;
            #pragma unroll 4
            for (int k = 0; k < HID; k += 4) {
                const float4 xa = *(const float4*)(xg + k);
                const float4 wa = *(const float4*)(wg + k);
                s0 += xa.x * wa.x; s1 += xa.y * wa.y;
                s2 += xa.z * wa.z; s3 += xa.w * wa.w;
            }
            ev[c] = (s0 + s1) + (s2 + s3);
        }
    }

    // re-rank candidates on exact values (tie -> lower expert index)
    int b1 = 0;
    #pragma unroll
    for (int c = 1; c < 4; c++)
        if (ev[c] > ev[b1] || (ev[c] == ev[b1] && tix[c] < tix[b1])) b1 = c;
    int b2 = (b1 == 0) ? 1 : 0;
    #pragma unroll
    for (int c = 0; c < 4; c++) {
        if (c == b1 || c == b2) continue;
        if (ev[c] > ev[b2] || (ev[c] == ev[b2] && tix[c] < tix[b2])) b2 = c;
    }

    // softmax over mma logits (for aux only); store unnormalized, scale later
    float Z = 0.0f;
    const float mx = tv[0];
    #pragma unroll 8
    for (int e = 0; e < NE; e++) {
        const float pe = __expf(L[tid * 65 + e] - mx);
        Z += pe;
        L[tid * 65 + e] = pe;
    }
    rzs[tid] = 1.0f / Z;

    {
        out[2 * gt + 0] = (float)tix[b1];
        out[2 * gt + 1] = (float)tix[b2];
        const float r = expf(ev[b2] - ev[b1]);      // <= 1
        const float inv = 1.0f / (1.0f + r);
        out[2 * NTOK + 2 * gt + 0] = inv;           // p1/(p1+p2)
        out[2 * NTOK + 2 * gt + 1] = r * inv;       // p2/(p1+p2)
        atomicAdd(&cnt_s[tix[b1]], 1);
        atomicAdd(&cnt_s[tix[b2]], 1);
    }
    __syncthreads();

    // per-expert normalized-prob sums over the 128 tokens
    {
        const int e = tid & 63, h = tid >> 6;
        float s = 0.0f;
        #pragma unroll 8
        for (int r2 = h * 64; r2 < h * 64 + 64; r2++) s += L[r2 * 65 + e] * rzs[r2];
        psum[tid] = s;
    }
    __syncthreads();
    if (tid < NE) {
        const int b = tok0 >> 12;
        atomicAdd(&g_ssum[b * NE + tid], psum[tid] + psum[64 + tid]);
        atomicAdd(&g_cnt [b * NE + tid], cnt_s[tid]);
    }
}

__global__ void aux_kernel(float* __restrict__ out) {
    int t = threadIdx.x;  // 256 = NBATCH*NE
    float v = ((float)g_cnt[t] * ((float)NE / (float)(SEQ * 2))) *
              (g_ssum[t] / (float)SEQ);
    #pragma unroll
    for (int o = 16; o; o >>= 1) v += __shfl_xor_sync(0xffffffffu, v, o);
    __shared__ float wsum[8];
    if ((t & 31) == 0) wsum[t >> 5] = v;
    __syncthreads();
    if (t < 8) {
        float s = wsum[t];
        #pragma unroll
        for (int o = 4; o; o >>= 1) s += __shfl_xor_sync(0xffu, s, o);
        if (t == 0) out[4 * NTOK] = 0.01f * s / (float)NBATCH;
    }
}

extern "C" void kernel_launch(void* const* d_in, const int* in_sizes, int n_in,
                              void* d_out, int out_size) {
    const float* x = (const float*)d_in[0];
    const float* w = (const float*)d_in[1];
    float* out = (float*)d_out;

    static int configured = 0;
    if (!configured) {
        cudaFuncSetAttribute(gate_kernel, cudaFuncAttributeMaxDynamicSharedMemorySize, DSM_BYTES);
        configured = 1;
    }
    zero_kernel<<<1, 256>>>();
    gate_kernel<<<NTOK / TTILE, 128, DSM_BYTES>>>(x, w, out);
    aux_kernel<<<1, 256>>>(out);
}

// round 13
// speedup vs baseline: 2.6330x; 2.6330x over previous
#include <cuda_runtime.h>
#include <cstdint>

#define NBATCH 4
#define SEQ    4096
#define HID    2048
#define NE     64
#define NTOK   (NBATCH * SEQ)   // 16384
#define TTILE  128
#define KC     32
#define NCHUNK (HID / KC)       // 64
#define TAU    1e-3f

// dynamic smem (floats): Ah[4096] Al[4096] Bh[2048] Bl[2048]
#define OFF_AH 0
#define OFF_AL 4096
#define OFF_BH 8192
#define OFF_BL 10240
#define DSM_FLOATS 12288
#define DSM_BYTES  (DSM_FLOATS * 4)   // 49152

__device__ float g_wbh[NCHUNK * 2048];   // w hi, fragment layout per chunk
__device__ float g_wbl[NCHUNK * 2048];   // w lo
__device__ float g_ssum[NBATCH * NE];
__device__ int   g_cnt [NBATCH * NE];

__device__ __forceinline__ float tf32f(float v) {
    float r; asm("cvt.rna.tf32.f32 %0, %1;" : "=f"(r) : "f"(v)); return r;
}
__device__ __forceinline__ void mma8(float* d, const uint32_t* a, const uint32_t* b) {
    asm volatile(
        "mma.sync.aligned.m16n8k8.row.col.f32.tf32.tf32.f32 "
        "{%0,%1,%2,%3}, {%4,%5,%6,%7}, {%8,%9}, {%0,%1,%2,%3};"
        : "+f"(d[0]), "+f"(d[1]), "+f"(d[2]), "+f"(d[3])
        : "r"(a[0]), "r"(a[1]), "r"(a[2]), "r"(a[3]), "r"(b[0]), "r"(b[1]));
}

// precompute w hi/lo in fragment layout: entry idx of chunk t:
// fB = idx>>6 (ks*8+nt), li = idx&63, lane = li>>1, reg = li&1
// value = w[nt*8 + lane/4][t*32 + ks*8 + reg*4 + lane%4]
__global__ void wprep_kernel(const float* __restrict__ w) {
    const int t = blockIdx.x;
    if (t == 0 && threadIdx.x < NBATCH * NE) {
        g_ssum[threadIdx.x] = 0.0f; g_cnt[threadIdx.x] = 0;
    }
    #pragma unroll
    for (int it = 0; it < 8; it++) {
        const int idx = threadIdx.x + it * 256;       // 0..2047
        const int fB = idx >> 6, li = idx & 63;
        const int ks = fB >> 3, nt = fB & 7;
        const int lane = li >> 1, reg = li & 1;
        const int e = nt * 8 + (lane >> 2);
        const int k = t * 32 + ks * 8 + reg * 4 + (lane & 3);
        const float v = w[(size_t)e * HID + k];
        const float hi = tf32f(v);
        g_wbh[t * 2048 + idx] = hi;
        g_wbl[t * 2048 + idx] = tf32f(v - hi);
    }
}

extern __shared__ float dsm[];

__global__ __launch_bounds__(256, 1)
void gate_kernel(const float* __restrict__ x, const float* __restrict__ w,
                 float* __restrict__ out)
{
    const int tid = threadIdx.x;
    const int lane = tid & 31, warp = tid >> 5;
    const int tok0 = blockIdx.x * TTILE;

    __shared__ int   cnt_s[NE];
    __shared__ float psum[256];
    __shared__ float rzs[128];
    __shared__ int   cand[128][4];
    __shared__ float evx[128][4];
    if (tid < NE) cnt_s[tid] = 0;

    float* Ah = dsm + OFF_AH;
    float* Al = dsm + OFF_AL;
    float* Bh = dsm + OFF_BH;
    float* Bl = dsm + OFF_BL;

    float acc[8][4];
    #pragma unroll
    for (int nt = 0; nt < 8; nt++)
        #pragma unroll
        for (int r = 0; r < 4; r++) acc[nt][r] = 0.0f;

    // A staging: thread handles half a token row (16 k per chunk)
    const int stok = tid >> 1, skh = tid & 1;
    const float* xrow = x + (size_t)(tok0 + stok) * HID + skh * 16;
    const int s_r0  = ((stok & 15) >= 8) ? 1 : 0;
    const int s_ln0 = (stok & 7) * 4;
    const int s_amt = stok >> 4;

    float4 xr[4];
    #pragma unroll
    for (int i = 0; i < 4; i++) xr[i] = *(const float4*)(xrow + i * 4);

    for (int t = 0; t < NCHUNK; t++) {
        // ---- stage A (cvt hi/lo into fragment layout) ----
        #pragma unroll
        for (int i = 0; i < 4; i++) {
            const float v[4] = {xr[i].x, xr[i].y, xr[i].z, xr[i].w};
            #pragma unroll
            for (int j = 0; j < 4; j++) {
                const int k = skh * 16 + i * 4 + j;
                const int kstep = k >> 3, klo = k & 7;
                const int r = s_r0 + ((klo >= 4) ? 2 : 0);
                const int ad = (kstep * 8 + s_amt) * 128 + (s_ln0 + (klo & 3)) * 4 + r;
                const float h = tf32f(v[j]);
                Ah[ad] = h;
                Al[ad] = tf32f(v[j] - h);
            }
        }
        // ---- stage B (linear copy from precomputed global) ----
        #pragma unroll
        for (int it = 0; it < 2; it++) {
            const int i4 = tid + it * 256;             // 0..511 float4 per plane
            *(float4*)(Bh + i4 * 4) = *(const float4*)(g_wbh + t * 2048 + i4 * 4);
            *(float4*)(Bl + i4 * 4) = *(const float4*)(g_wbl + t * 2048 + i4 * 4);
        }
        __syncthreads();

        // prefetch next x half-row
        if (t + 1 < NCHUNK) {
            #pragma unroll
            for (int i = 0; i < 4; i++)
                xr[i] = *(const float4*)(xrow + (t + 1) * 32 + i * 4);
        }

        // ---- compute: 4 k-steps x (8 nt x 3 passes) ----
        #pragma unroll
        for (int ks = 0; ks < 4; ks++) {
            const int fA = ks * 8 + warp;
            const uint4 AHv = *(const uint4*)(Ah + fA * 128 + lane * 4);
            const uint4 ALv = *(const uint4*)(Al + fA * 128 + lane * 4);
            uint2 BHv[8], BLv[8];
            #pragma unroll
            for (int nt = 0; nt < 8; nt++) {
                const int fB = ks * 8 + nt;
                BHv[nt] = *(const uint2*)(Bh + fB * 64 + lane * 2);
                BLv[nt] = *(const uint2*)(Bl + fB * 64 + lane * 2);
            }
            #pragma unroll
            for (int nt = 0; nt < 8; nt++) mma8(acc[nt], &AHv.x, &BHv[nt].x);
            #pragma unroll
            for (int nt = 0; nt < 8; nt++) mma8(acc[nt], &AHv.x, &BLv[nt].x);
            #pragma unroll
            for (int nt = 0; nt < 8; nt++) mma8(acc[nt], &ALv.x, &BHv[nt].x);
        }
        __syncthreads();
    }

    // ---- dump logits to smem, pitch 65 ----
    float* L = dsm;
    {
        const int row0 = warp * 16 + (lane >> 2);
        const int ec = (lane & 3) * 2;
        #pragma unroll
        for (int nt = 0; nt < 8; nt++) {
            const int e0 = nt * 8 + ec;
            L[row0 * 65 + e0]           = acc[nt][0];
            L[row0 * 65 + e0 + 1]       = acc[nt][1];
            L[(row0 + 8) * 65 + e0]     = acc[nt][2];
            L[(row0 + 8) * 65 + e0 + 1] = acc[nt][3];
        }
    }
    __syncthreads();

    // ---- per-token: top-4 scan, flag ambiguity, softmax (threads 0..127) ----
    float tv[4] = {-1e30f, -1e30f, -1e30f, -1e30f};
    int   tix[4] = {0, 0, 0, 0};
    bool  flag = false;
    if (tid < 128) {
        for (int e = 0; e < NE; e++) {
            const float Le = L[tid * 65 + e];
            if (Le > tv[3]) {
                int p = 3;
                while (p > 0 && Le > tv[p - 1]) {
                    tv[p] = tv[p - 1]; tix[p] = tix[p - 1]; p--;
                }
                tv[p] = Le; tix[p] = e;
            }
        }
        flag = (tv[0] - tv[1] < TAU) || (tv[1] - tv[2] < TAU);
        #pragma unroll
        for (int c = 0; c < 4; c++) cand[tid][c] = tix[c];

        float Z = 0.0f;
        const float mx = tv[0];
        #pragma unroll 8
        for (int e = 0; e < NE; e++) {
            const float pe = __expf(L[tid * 65 + e] - mx);
            Z += pe;
            L[tid * 65 + e] = pe;
        }
        rzs[tid] = 1.0f / Z;
    }
    __syncthreads();

    // ---- warp-cooperative exact recompute of flagged tokens (warps 0..3) ----
    if (warp < 4) {
        unsigned mask = __ballot_sync(0xffffffffu, flag);
        while (mask) {
            const int b = __ffs(mask) - 1; mask &= mask - 1;
            const int tk = warp * 32 + b;
            const float* xg = x + (size_t)(tok0 + tk) * HID;
            const int c0 = cand[tk][0], c1 = cand[tk][1],
                      c2 = cand[tk][2], c3 = cand[tk][3];
            float s0 = 0.f, s1 = 0.f, s2 = 0.f, s3 = 0.f;
            for (int k0 = lane * 4; k0 < HID; k0 += 128) {
                const float4 xa = *(const float4*)(xg + k0);
                const float4 w0 = *(const float4*)(w + (size_t)c0 * HID + k0);
                const float4 w1 = *(const float4*)(w + (size_t)c1 * HID + k0);
                const float4 w2 = *(const float4*)(w + (size_t)c2 * HID + k0);
                const float4 w3 = *(const float4*)(w + (size_t)c3 * HID + k0);
                s0 += xa.x*w0.x + xa.y*w0.y + xa.z*w0.z + xa.w*w0.w;
                s1 += xa.x*w1.x + xa.y*w1.y + xa.z*w1.z + xa.w*w1.w;
                s2 += xa.x*w2.x + xa.y*w2.y + xa.z*w2.z + xa.w*w2.w;
                s3 += xa.x*w3.x + xa.y*w3.y + xa.z*w3.z + xa.w*w3.w;
            }
            #pragma unroll
            for (int o = 16; o; o >>= 1) {
                s0 += __shfl_xor_sync(0xffffffffu, s0, o);
                s1 += __shfl_xor_sync(0xffffffffu, s1, o);
                s2 += __shfl_xor_sync(0xffffffffu, s2, o);
                s3 += __shfl_xor_sync(0xffffffffu, s3, o);
            }
            if (lane == 0) {
                evx[tk][0] = s0; evx[tk][1] = s1; evx[tk][2] = s2; evx[tk][3] = s3;
            }
        }
    }
    __syncthreads();

    // ---- finalize outputs (threads 0..127) ----
    if (tid < 128) {
        float ev[4];
        #pragma unroll
        for (int c = 0; c < 4; c++) ev[c] = flag ? evx[tid][c] : tv[c];

        int b1 = 0;
        #pragma unroll
        for (int c = 1; c < 4; c++)
            if (ev[c] > ev[b1] || (ev[c] == ev[b1] && tix[c] < tix[b1])) b1 = c;
        int b2 = (b1 == 0) ? 1 : 0;
        #pragma unroll
        for (int c = 0; c < 4; c++) {
            if (c == b1 || c == b2) continue;
            if (ev[c] > ev[b2] || (ev[c] == ev[b2] && tix[c] < tix[b2])) b2 = c;
        }

        const int gt = tok0 + tid;
        out[2 * gt + 0] = (float)tix[b1];
        out[2 * gt + 1] = (float)tix[b2];
        const float r = expf(ev[b2] - ev[b1]);      // <= 1
        const float inv = 1.0f / (1.0f + r);
        out[2 * NTOK + 2 * gt + 0] = inv;
        out[2 * NTOK + 2 * gt + 1] = r * inv;
        atomicAdd(&cnt_s[tix[b1]], 1);
        atomicAdd(&cnt_s[tix[b2]], 1);
    }
    __syncthreads();

    // ---- per-expert normalized-prob sums (all 256 threads) ----
    {
        const int e = tid & 63, h = tid >> 6;       // h in 0..3, 32 rows each
        float s = 0.0f;
        #pragma unroll 8
        for (int r2 = h * 32; r2 < h * 32 + 32; r2++) s += L[r2 * 65 + e] * rzs[r2];
        psum[tid] = s;
    }
    __syncthreads();
    if (tid < NE) {
        const int b = tok0 >> 12;
        atomicAdd(&g_ssum[b * NE + tid],
                  psum[tid] + psum[64 + tid] + psum[128 + tid] + psum[192 + tid]);
        atomicAdd(&g_cnt[b * NE + tid], cnt_s[tid]);
    }
}

__global__ void aux_kernel(float* __restrict__ out) {
    int t = threadIdx.x;  // 256 = NBATCH*NE
    float v = ((float)g_cnt[t] * ((float)NE / (float)(SEQ * 2))) *
              (g_ssum[t] / (float)SEQ);
    #pragma unroll
    for (int o = 16; o; o >>= 1) v += __shfl_xor_sync(0xffffffffu, v, o);
    __shared__ float wsum[8];
    if ((t & 31) == 0) wsum[t >> 5] = v;
    __syncthreads();
    if (t < 8) {
        float s = wsum[t];
        #pragma unroll
        for (int o = 4; o; o >>= 1) s += __shfl_xor_sync(0xffu, s, o);
        if (t == 0) out[4 * NTOK] = 0.01f * s / (float)NBATCH;
    }
}

extern "C" void kernel_launch(void* const* d_in, const int* in_sizes, int n_in,
                              void* d_out, int out_size) {
    const float* x = (const float*)d_in[0];
    const float* w = (const float*)d_in[1];
    float* out = (float*)d_out;

    static int configured = 0;
    if (!configured) {
        cudaFuncSetAttribute(gate_kernel, cudaFuncAttributeMaxDynamicSharedMemorySize, DSM_BYTES);
        configured = 1;
    }
    wprep_kernel<<<NCHUNK, 256>>>(w);
    gate_kernel<<<NTOK / TTILE, 256, DSM_BYTES>>>(x, w, out);
    aux_kernel<<<1, 256>>>(out);
}

// round 14
// speedup vs baseline: 3.9203x; 1.4889x over previous
#include <cuda_runtime.h>
#include <cuda_fp16.h>
#include <cstdint>

#define NBATCH 4
#define SEQ    4096
#define HID    2048
#define NE     64
#define NTOK   (NBATCH * SEQ)   // 16384
#define TTILE  128
#define KC     32
#define NCHUNK (HID / KC)       // 64
#define TAU    1e-3f
#define WSCALE 64.0f
#define RSCALE (1.0f / 64.0f)

// dynamic smem (uint32 units): Ah[2048] Al[2048] Bh[1024] Bl[1024] = 24KB
// logits overlay needs 128*65 floats = 33280B -> DSM = 33280
#define OFF_AH 0
#define OFF_AL 2048
#define OFF_BH 4096
#define OFF_BL 5120
#define DSM_BYTES 33280

__device__ uint32_t g_wbh[NCHUNK * 1024];   // w*64 hi fp16x2, fragment layout
__device__ uint32_t g_wbl[NCHUNK * 1024];   // w*64 lo fp16x2
__device__ float g_ssum[NBATCH * NE];
__device__ int   g_cnt [NBATCH * NE];

__device__ __forceinline__ void mma16(float* d, const uint32_t* a, const uint32_t* b) {
    asm volatile(
        "mma.sync.aligned.m16n8k16.row.col.f32.f16.f16.f32 "
        "{%0,%1,%2,%3}, {%4,%5,%6,%7}, {%8,%9}, {%0,%1,%2,%3};"
        : "+f"(d[0]), "+f"(d[1]), "+f"(d[2]), "+f"(d[3])
        : "r"(a[0]), "r"(a[1]), "r"(a[2]), "r"(a[3]), "r"(b[0]), "r"(b[1]));
}
__device__ __forceinline__ uint32_t hilo_pack(float v0, float v1, uint32_t& lo) {
    __half h0 = __float2half_rn(v0), h1 = __float2half_rn(v1);
    __half l0 = __float2half_rn(v0 - __half2float(h0));
    __half l1 = __float2half_rn(v1 - __half2float(h1));
    __half2 H = __halves2half2(h0, h1), L = __halves2half2(l0, l1);
    lo = *(uint32_t*)&L;
    return *(uint32_t*)&H;
}

// precompute w*64 hi/lo fp16x2 in fragment layout; entry idx (0..1023) of chunk t:
// r = idx&1, l = (idx>>1)&31, fB = idx>>6 (= ks*8+nt)
// e = nt*8 + (l>>2); k = t*32 + ks*16 + ((l&3) + r*4)*2 + {0,1}
__global__ void wprep_kernel(const float* __restrict__ w) {
    const int t = blockIdx.x;
    if (t == 0 && threadIdx.x < NBATCH * NE) {
        g_ssum[threadIdx.x] = 0.0f; g_cnt[threadIdx.x] = 0;
    }
    #pragma unroll
    for (int it = 0; it < 4; it++) {
        const int idx = threadIdx.x + it * 256;
        const int r = idx & 1, l = (idx >> 1) & 31, fB = idx >> 6;
        const int nt = fB & 7, ks = fB >> 3;
        const int e = nt * 8 + (l >> 2);
        const int k = t * 32 + ks * 16 + ((l & 3) + r * 4) * 2;
        const float v0 = w[(size_t)e * HID + k]     * WSCALE;
        const float v1 = w[(size_t)e * HID + k + 1] * WSCALE;
        uint32_t lo, hi = hilo_pack(v0, v1, lo);
        g_wbh[t * 1024 + idx] = hi;
        g_wbl[t * 1024 + idx] = lo;
    }
}

extern __shared__ uint32_t dsmu[];

__global__ __launch_bounds__(256, 1)
void gate_kernel(const float* __restrict__ x, const float* __restrict__ w,
                 float* __restrict__ out)
{
    const int tid = threadIdx.x;
    const int lane = tid & 31, warp = tid >> 5;
    const int tok0 = blockIdx.x * TTILE;

    __shared__ int   cnt_s[NE];
    __shared__ float psum[256];
    __shared__ float rzs[128];
    __shared__ int   cand[128][4];
    __shared__ float evx[128][4];
    if (tid < NE) cnt_s[tid] = 0;

    uint32_t* Ah = dsmu + OFF_AH;
    uint32_t* Al = dsmu + OFF_AL;
    uint32_t* Bh = dsmu + OFF_BH;
    uint32_t* Bl = dsmu + OFF_BL;

    float acc[8][4];
    #pragma unroll
    for (int nt = 0; nt < 8; nt++)
        #pragma unroll
        for (int r = 0; r < 4; r++) acc[nt][r] = 0.0f;

    // A staging: thread owns token stok, k-half skh (16 k = kstep skh)
    const int stok = tid >> 1, skh = tid & 1;
    const float* xrow = x + (size_t)(tok0 + stok) * HID + skh * 16;
    const int ri = stok & 15, mt = stok >> 4;
    const int fA_s = skh * 8 + mt;
    const int rbase = (ri >= 8) ? 1 : 0;
    const int lbase = (ri & 7) * 4;

    float4 xr[4];
    uint4  bph, bpl;
    #pragma unroll
    for (int i = 0; i < 4; i++) xr[i] = *(const float4*)(xrow + i * 4);
    bph = *(const uint4*)(g_wbh + tid * 4);
    bpl = *(const uint4*)(g_wbl + tid * 4);

    for (int t = 0; t < NCHUNK; t++) {
        // ---- stage A (fp16 hi/lo pairs into fragment layout) ----
        #pragma unroll
        for (int i = 0; i < 4; i++) {
            const float v[4] = {xr[i].x, xr[i].y, xr[i].z, xr[i].w};
            #pragma unroll
            for (int jj = 0; jj < 2; jj++) {
                const int p = i * 2 + jj;                 // kpair 0..7
                uint32_t lo, hi = hilo_pack(v[jj * 2], v[jj * 2 + 1], lo);
                const int reg = rbase + ((p >= 4) ? 2 : 0);
                const int ad  = fA_s * 128 + (lbase + (p & 3)) * 4 + reg;
                Ah[ad] = hi;
                Al[ad] = lo;
            }
        }
        // ---- stage B (prefetched uint4 -> linear store) ----
        ((uint4*)Bh)[tid] = bph;
        ((uint4*)Bl)[tid] = bpl;
        __syncthreads();

        // prefetch next chunk (x raw + B planes)
        if (t + 1 < NCHUNK) {
            #pragma unroll
            for (int i = 0; i < 4; i++)
                xr[i] = *(const float4*)(xrow + (t + 1) * 32 + i * 4);
            bph = *(const uint4*)(g_wbh + (t + 1) * 1024 + tid * 4);
            bpl = *(const uint4*)(g_wbl + (t + 1) * 1024 + tid * 4);
        }

        // ---- compute: 2 k-steps x (8 nt x 3 passes) ----
        #pragma unroll
        for (int ks = 0; ks < 2; ks++) {
            const int fA = ks * 8 + warp;
            const uint4 AHv = *(const uint4*)(Ah + fA * 128 + lane * 4);
            const uint4 ALv = *(const uint4*)(Al + fA * 128 + lane * 4);
            uint2 BHv[8], BLv[8];
            #pragma unroll
            for (int nt = 0; nt < 8; nt++) {
                const int fB = ks * 8 + nt;
                BHv[nt] = *(const uint2*)(Bh + fB * 64 + lane * 2);
                BLv[nt] = *(const uint2*)(Bl + fB * 64 + lane * 2);
            }
            #pragma unroll
            for (int nt = 0; nt < 8; nt++) mma16(acc[nt], &AHv.x, &BHv[nt].x);
            #pragma unroll
            for (int nt = 0; nt < 8; nt++) mma16(acc[nt], &AHv.x, &BLv[nt].x);
            #pragma unroll
            for (int nt = 0; nt < 8; nt++) mma16(acc[nt], &ALv.x, &BHv[nt].x);
        }
        __syncthreads();
    }

    // ---- dump logits (rescaled) to smem, pitch 65 ----
    float* L = (float*)dsmu;
    {
        const int row0 = warp * 16 + (lane >> 2);
        const int ec = (lane & 3) * 2;
        #pragma unroll
        for (int nt = 0; nt < 8; nt++) {
            const int e0 = nt * 8 + ec;
            L[row0 * 65 + e0]           = acc[nt][0] * RSCALE;
            L[row0 * 65 + e0 + 1]       = acc[nt][1] * RSCALE;
            L[(row0 + 8) * 65 + e0]     = acc[nt][2] * RSCALE;
            L[(row0 + 8) * 65 + e0 + 1] = acc[nt][3] * RSCALE;
        }
    }
    __syncthreads();

    // ---- per-token: top-4 scan, flag ambiguity, softmax (threads 0..127) ----
    float tv[4] = {-1e30f, -1e30f, -1e30f, -1e30f};
    int   tix[4] = {0, 0, 0, 0};
    bool  flag = false;
    if (tid < 128) {
        for (int e = 0; e < NE; e++) {
            const float Le = L[tid * 65 + e];
            if (Le > tv[3]) {
                int p = 3;
                while (p > 0 && Le > tv[p - 1]) {
                    tv[p] = tv[p - 1]; tix[p] = tix[p - 1]; p--;
                }
                tv[p] = Le; tix[p] = e;
            }
        }
        flag = (tv[0] - tv[1] < TAU) || (tv[1] - tv[2] < TAU);
        #pragma unroll
        for (int c = 0; c < 4; c++) cand[tid][c] = tix[c];

        float Z = 0.0f;
        const float mx = tv[0];
        #pragma unroll 8
        for (int e = 0; e < NE; e++) {
            const float pe = __expf(L[tid * 65 + e] - mx);
            Z += pe;
            L[tid * 65 + e] = pe;
        }
        rzs[tid] = 1.0f / Z;
    }
    __syncthreads();

    // ---- warp-cooperative exact fp32 recompute of flagged tokens ----
    if (warp < 4) {
        unsigned mask = __ballot_sync(0xffffffffu, flag);
        while (mask) {
            const int b = __ffs(mask) - 1; mask &= mask - 1;
            const int tk = warp * 32 + b;
            const float* xg = x + (size_t)(tok0 + tk) * HID;
            const int c0 = cand[tk][0], c1 = cand[tk][1],
                      c2 = cand[tk][2], c3 = cand[tk][3];
            float s0 = 0.f, s1 = 0.f, s2 = 0.f, s3 = 0.f;
            for (int k0 = lane * 4; k0 < HID; k0 += 128) {
                const float4 xa = *(const float4*)(xg + k0);
                const float4 w0 = *(const float4*)(w + (size_t)c0 * HID + k0);
                const float4 w1 = *(const float4*)(w + (size_t)c1 * HID + k0);
                const float4 w2 = *(const float4*)(w + (size_t)c2 * HID + k0);
                const float4 w3 = *(const float4*)(w + (size_t)c3 * HID + k0);
                s0 += xa.x*w0.x + xa.y*w0.y + xa.z*w0.z + xa.w*w0.w;
                s1 += xa.x*w1.x + xa.y*w1.y + xa.z*w1.z + xa.w*w1.w;
                s2 += xa.x*w2.x + xa.y*w2.y + xa.z*w2.z + xa.w*w2.w;
                s3 += xa.x*w3.x + xa.y*w3.y + xa.z*w3.z + xa.w*w3.w;
            }
            #pragma unroll
            for (int o = 16; o; o >>= 1) {
                s0 += __shfl_xor_sync(0xffffffffu, s0, o);
                s1 += __shfl_xor_sync(0xffffffffu, s1, o);
                s2 += __shfl_xor_sync(0xffffffffu, s2, o);
                s3 += __shfl_xor_sync(0xffffffffu, s3, o);
            }
            if (lane == 0) {
                evx[tk][0] = s0; evx[tk][1] = s1; evx[tk][2] = s2; evx[tk][3] = s3;
            }
        }
    }
    __syncthreads();

    // ---- finalize outputs (threads 0..127) ----
    if (tid < 128) {
        float ev[4];
        #pragma unroll
        for (int c = 0; c < 4; c++) ev[c] = flag ? evx[tid][c] : tv[c];

        int b1 = 0;
        #pragma unroll
        for (int c = 1; c < 4; c++)
            if (ev[c] > ev[b1] || (ev[c] == ev[b1] && tix[c] < tix[b1])) b1 = c;
        int b2 = (b1 == 0) ? 1 : 0;
        #pragma unroll
        for (int c = 0; c < 4; c++) {
            if (c == b1 || c == b2) continue;
            if (ev[c] > ev[b2] || (ev[c] == ev[b2] && tix[c] < tix[b2])) b2 = c;
        }

        const int gt = tok0 + tid;
        out[2 * gt + 0] = (float)tix[b1];
        out[2 * gt + 1] = (float)tix[b2];
        const float r = expf(ev[b2] - ev[b1]);
        const float inv = 1.0f / (1.0f + r);
        out[2 * NTOK + 2 * gt + 0] = inv;
        out[2 * NTOK + 2 * gt + 1] = r * inv;
        atomicAdd(&cnt_s[tix[b1]], 1);
        atomicAdd(&cnt_s[tix[b2]], 1);
    }
    __syncthreads();

    // ---- per-expert normalized-prob sums (all 256 threads) ----
    {
        const int e = tid & 63, h = tid >> 6;
        float s = 0.0f;
        float* L2 = (float*)dsmu;
        #pragma unroll 8
        for (int r2 = h * 32; r2 < h * 32 + 32; r2++) s += L2[r2 * 65 + e] * rzs[r2];
        psum[tid] = s;
    }
    __syncthreads();
    if (tid < NE) {
        const int b = tok0 >> 12;
        atomicAdd(&g_ssum[b * NE + tid],
                  psum[tid] + psum[64 + tid] + psum[128 + tid] + psum[192 + tid]);
        atomicAdd(&g_cnt[b * NE + tid], cnt_s[tid]);
    }
}

__global__ void aux_kernel(float* __restrict__ out) {
    int t = threadIdx.x;  // 256 = NBATCH*NE
    float v = ((float)g_cnt[t] * ((float)NE / (float)(SEQ * 2))) *
              (g_ssum[t] / (float)SEQ);
    #pragma unroll
    for (int o = 16; o; o >>= 1) v += __shfl_xor_sync(0xffffffffu, v, o);
    __shared__ float wsum[8];
    if ((t & 31) == 0) wsum[t >> 5] = v;
    __syncthreads();
    if (t < 8) {
        float s = wsum[t];
        #pragma unroll
        for (int o = 4; o; o >>= 1) s += __shfl_xor_sync(0xffu, s, o);
        if (t == 0) out[4 * NTOK] = 0.01f * s / (float)NBATCH;
    }
}

extern "C" void kernel_launch(void* const* d_in, const int* in_sizes, int n_in,
                              void* d_out, int out_size) {
    const float* x = (const float*)d_in[0];
    const float* w = (const float*)d_in[1];
    float* out = (float*)d_out;

    static int configured = 0;
    if (!configured) {
        cudaFuncSetAttribute(gate_kernel, cudaFuncAttributeMaxDynamicSharedMemorySize, DSM_BYTES);
        configured = 1;
    }
    wprep_kernel<<<NCHUNK, 256>>>(w);
    gate_kernel<<<NTOK / TTILE, 256, DSM_BYTES>>>(x, w, out);
    aux_kernel<<<1, 256>>>(out);
}